// round 15
// baseline (speedup 1.0000x reference)
#include <cuda_runtime.h>
#include <cstdint>

#define NUSER 50000
#define NITEM 100000
#define NN    150000
#define DD    64
#define EE    2400000
#define SCAN_B 586          // ceil(NN/256)

// scratch: static device globals (no runtime allocation allowed)
__device__ float g_egoA[NN * DD];    // 38.4 MB (ego ping)
__device__ float g_egoB[NN * DD];    // 38.4 MB (ego pong)
__device__ int   g_rowptr[NN];       // per-block-partial exclusive scan of counts
__device__ int   g_bsum[SCAN_B];     // block offsets (exclusive)
__device__ int   g_cnt[NN];
__device__ int   g_cur[NN];
__device__ int   g_srows[EE];        // CSR-sorted rows (for edge-parallel gather)
__device__ int   g_scols[EE];        // CSR-sorted cols
__device__ float g_svals[EE];        // CSR-sorted vals

// ---------------------------------------------------------------------------
// init: egoA = concat(user,item); out[:,0:64] = ego (raw); zero CSR counters
// ---------------------------------------------------------------------------
__global__ void init_kernel(const float* __restrict__ ue,
                            const float* __restrict__ ie,
                            float* __restrict__ out) {
    int i4 = blockIdx.x * blockDim.x + threadIdx.x;
    if (i4 >= NN * 16) return;
    int row = i4 >> 4;
    int q   = i4 & 15;
    float4 v;
    if (row < NUSER) v = reinterpret_cast<const float4*>(ue)[i4];
    else             v = reinterpret_cast<const float4*>(ie)[i4 - NUSER * 16];
    reinterpret_cast<float4*>(g_egoA)[i4] = v;
    reinterpret_cast<float4*>(out)[row * 64 + q] = v;
    if (q == 0) { g_cnt[row] = 0; g_cur[row] = 0; }
}

// ---------------------------------------------------------------------------
// CSR build: histogram -> 2-level exclusive scan -> scatter
// ---------------------------------------------------------------------------
__global__ void hist_kernel(const int* __restrict__ rows) {
    int e = blockIdx.x * blockDim.x + threadIdx.x;
    if (e < EE) atomicAdd(&g_cnt[__ldg(rows + e)], 1);
}

__global__ void scan1_kernel() {        // grid SCAN_B, block 256
    __shared__ int s[256];
    int tx = threadIdx.x;
    int i  = blockIdx.x * 256 + tx;
    int v  = (i < NN) ? g_cnt[i] : 0;
    s[tx] = v;
    __syncthreads();
#pragma unroll
    for (int off = 1; off < 256; off <<= 1) {
        int t = (tx >= off) ? s[tx - off] : 0;
        __syncthreads();
        s[tx] += t;
        __syncthreads();
    }
    if (i < NN) g_rowptr[i] = s[tx] - v;          // block-local exclusive
    if (tx == 255) g_bsum[blockIdx.x] = s[255];   // block total
}

__global__ void scan2_kernel() {        // 1 block, 1024 threads
    __shared__ int s[1024];
    int tx = threadIdx.x;
    int v  = (tx < SCAN_B) ? g_bsum[tx] : 0;
    s[tx] = v;
    __syncthreads();
#pragma unroll
    for (int off = 1; off < 1024; off <<= 1) {
        int t = (tx >= off) ? s[tx - off] : 0;
        __syncthreads();
        s[tx] += t;
        __syncthreads();
    }
    if (tx < SCAN_B) g_bsum[tx] = s[tx] - v;      // exclusive block offsets
}

__global__ void scatter_kernel(const float* __restrict__ vals,
                               const int*   __restrict__ rows,
                               const int*   __restrict__ cols) {
    int e = blockIdx.x * blockDim.x + threadIdx.x;
    if (e >= EE) return;
    int r = __ldg(rows + e);
    int pos = g_rowptr[r] + g_bsum[r >> 8] + atomicAdd(&g_cur[r], 1);
    g_srows[pos] = r;
    g_scols[pos] = __ldg(cols + e);
    g_svals[pos] = __ldg(vals + e);
}

// ---------------------------------------------------------------------------
// tf32 helpers
// ---------------------------------------------------------------------------
__device__ __forceinline__ uint32_t f2tf32(float f) {
    uint32_t u;
    asm("cvt.rna.tf32.f32 %0, %1;" : "=r"(u) : "f"(f));
    return u;
}
__device__ __forceinline__ void split2(float f, float& hi, float& lo) {
    uint32_t h = f2tf32(f);
    hi = __uint_as_float(h);
    lo = __uint_as_float(f2tf32(f - hi));
}
__device__ __forceinline__ void splitu(float f, uint32_t& hi, uint32_t& lo) {
    hi = f2tf32(f);
    lo = f2tf32(f - __uint_as_float(hi));
}
__device__ __forceinline__ void mma_tf32(float c[4],
                                         uint32_t a0, uint32_t a1, uint32_t a2, uint32_t a3,
                                         uint32_t b0, uint32_t b1) {
    asm volatile(
        "mma.sync.aligned.m16n8k8.row.col.f32.tf32.tf32.f32 "
        "{%0,%1,%2,%3}, {%4,%5,%6,%7}, {%8,%9}, {%0,%1,%2,%3};"
        : "+f"(c[0]), "+f"(c[1]), "+f"(c[2]), "+f"(c[3])
        : "r"(a0), "r"(a1), "r"(a2), "r"(a3), "r"(b0), "r"(b1));
}

// swizzles (float-index): conflict-free mma fragment loads, float2/4-aligned
#define SW_A(r, c)  ((r) * 64 + ((c) ^ (((r) & 7) << 2)))
#define SW_W(k, n)  ((k) * 64 + ((n) ^ (((k) & 3) << 3)))

// float4 offsets in dynamic smem (64-row tile)
#define OFF4_WGH 0          // 64*16 = 1024 float4 each
#define OFF4_WGL 1024
#define OFF4_WBH 2048
#define OFF4_WBL 3072
#define OFF4_S   4096       // 64*16 = 1024 float4 each
#define OFF4_ES  5120
#define OFF4_SQ  6144       // 128 floats = 32 float4
#define SMEM_BYTES ((6176) * 16)   // 98816 B -> 2 blocks/SM

__device__ __forceinline__ int rowptr_abs(int r) {
    return (r < NN) ? (__ldg(&g_rowptr[r]) + __ldg(&g_bsum[r >> 8])) : EE;
}

// ---------------------------------------------------------------------------
// FUSED SpMM + dense layer (3xTF32 mma.sync m16n8k8):
//   Block = 256 thr / 8 warps, 64 rows.
//   Gather: EDGE-PARALLEL. Block's CSR edge range split evenly across the 8
//   warps; per edge: broadcast row/col/val + coalesced 256B ego gather +
//   2 smem float atomicAdds into the swizzled S tile. No loop-carried
//   dependency -> deep load pipelining; no row-length imbalance.
//   Then ES = ego*S, then the proven GEMM tile. ego double-buffered.
// ---------------------------------------------------------------------------
__global__ __launch_bounds__(256) void layer_fused(
    const float* __restrict__ src,
    const float* __restrict__ Wg, const float* __restrict__ bg,
    const float* __restrict__ Wb, const float* __restrict__ bb,
    float* __restrict__ dst, float* __restrict__ out, int koff) {
    extern __shared__ float sm[];
    float4* sm4 = reinterpret_cast<float4*>(sm);

    int tid = threadIdx.x;
    int rowbase = blockIdx.x * 64;

    // ---- stage weights, pre-split hi/lo, swizzled; zero S tile ----
#pragma unroll
    for (int i = 0; i < 4; i++) {
        int id = tid + i * 256;           // float4 id, 0..1023
        int k  = id >> 4, lc = id & 15;
        int sidx = k * 16 + (lc ^ ((k & 3) << 1));   // SW_W in float4 units
        float4 wg4 = reinterpret_cast<const float4*>(Wg)[id];
        float4 wb4 = reinterpret_cast<const float4*>(Wb)[id];
        float4 h, l;
        split2(wg4.x, h.x, l.x); split2(wg4.y, h.y, l.y);
        split2(wg4.z, h.z, l.z); split2(wg4.w, h.w, l.w);
        sm4[OFF4_WGH + sidx] = h;
        sm4[OFF4_WGL + sidx] = l;
        split2(wb4.x, h.x, l.x); split2(wb4.y, h.y, l.y);
        split2(wb4.z, h.z, l.z); split2(wb4.w, h.w, l.w);
        sm4[OFF4_WBH + sidx] = h;
        sm4[OFF4_WBL + sidx] = l;
        sm4[OFF4_S + id] = make_float4(0.f, 0.f, 0.f, 0.f);
    }
    __syncthreads();

    int warp = tid >> 5;
    int lane = tid & 31;
    const float2* ego2 = reinterpret_cast<const float2*>(src);
    float* sSw = sm + OFF4_S * 4;

    // ---- edge-parallel gather into smem S (atomic) ----
    {
        int Rb = rowptr_abs(rowbase);
        int Re = rowptr_abs((rowbase + 64 < NN) ? rowbase + 64 : NN);
        int cnt = Re - Rb;
        int chunk = (cnt + 7) >> 3;
        int eb = Rb + warp * chunk;
        int ee_ = eb + chunk; if (ee_ > Re) ee_ = Re;
        int e = eb;
        for (; e + 4 <= ee_; e += 4) {
            int   r0 = __ldg(g_srows + e),     r1 = __ldg(g_srows + e + 1);
            int   r2 = __ldg(g_srows + e + 2), r3 = __ldg(g_srows + e + 3);
            int   c0 = __ldg(g_scols + e),     c1 = __ldg(g_scols + e + 1);
            int   c2 = __ldg(g_scols + e + 2), c3 = __ldg(g_scols + e + 3);
            float v0 = __ldg(g_svals + e),     v1 = __ldg(g_svals + e + 1);
            float v2 = __ldg(g_svals + e + 2), v3 = __ldg(g_svals + e + 3);
            float2 x0 = __ldg(&ego2[c0 * 32 + lane]);
            float2 x1 = __ldg(&ego2[c1 * 32 + lane]);
            float2 x2 = __ldg(&ego2[c2 * 32 + lane]);
            float2 x3 = __ldg(&ego2[c3 * 32 + lane]);
            int i0 = SW_A(r0 - rowbase, 2 * lane);
            int i1 = SW_A(r1 - rowbase, 2 * lane);
            int i2 = SW_A(r2 - rowbase, 2 * lane);
            int i3 = SW_A(r3 - rowbase, 2 * lane);
            atomicAdd(&sSw[i0], v0 * x0.x); atomicAdd(&sSw[i0 + 1], v0 * x0.y);
            atomicAdd(&sSw[i1], v1 * x1.x); atomicAdd(&sSw[i1 + 1], v1 * x1.y);
            atomicAdd(&sSw[i2], v2 * x2.x); atomicAdd(&sSw[i2 + 1], v2 * x2.y);
            atomicAdd(&sSw[i3], v3 * x3.x); atomicAdd(&sSw[i3 + 1], v3 * x3.y);
        }
        for (; e < ee_; e++) {
            int   r0 = __ldg(g_srows + e);
            int   c0 = __ldg(g_scols + e);
            float v0 = __ldg(g_svals + e);
            float2 x0 = __ldg(&ego2[c0 * 32 + lane]);
            int i0 = SW_A(r0 - rowbase, 2 * lane);
            atomicAdd(&sSw[i0], v0 * x0.x); atomicAdd(&sSw[i0 + 1], v0 * x0.y);
        }
    }
    __syncthreads();

    // ---- ES = ego * S ----
    for (int rr = 0; rr < 8; rr++) {
        int lr = warp * 8 + rr;
        int grow = rowbase + lr;
        int fidx = SW_A(lr, 2 * lane);
        float2 es = make_float2(0.f, 0.f);
        if (grow < NN) {
            float2 ev = __ldg(&ego2[grow * 32 + lane]);
            es.x = ev.x * sSw[fidx];
            es.y = ev.y * sSw[fidx + 1];
        }
        *reinterpret_cast<float2*>(&sm[OFF4_ES * 4 + fidx]) = es;
    }
    __syncthreads();

    const float* sS   = sm + OFF4_S   * 4;
    const float* sES  = sm + OFF4_ES  * 4;
    const float* sWGH = sm + OFF4_WGH * 4;
    const float* sWGL = sm + OFF4_WGL * 4;
    const float* sWBH = sm + OFF4_WBH * 4;
    const float* sWBL = sm + OFF4_WBL * 4;
    float*       sSQ  = sm + OFF4_SQ  * 4;

    int wy = warp & 1;        // col half
    int wx = warp >> 1;       // row group 0..3
    int g  = lane >> 2;       // 0..7
    int c  = lane & 3;        // 0..3
    int r0 = wx * 16;
    int nb = wy * 32;

    float cg[4][4], cb[4][4];
#pragma unroll
    for (int nt = 0; nt < 4; nt++)
#pragma unroll
        for (int i = 0; i < 4; i++) { cg[nt][i] = 0.f; cb[nt][i] = 0.f; }

#pragma unroll
    for (int k = 0; k < 8; k++) {
        int k8 = k * 8;
        int rA = r0 + g, rB = r0 + g + 8;
        int c0_ = k8 + c, c1_ = k8 + c + 4;
        uint32_t sh[4], sl[4], eh[4], el[4];
        splitu(sS [SW_A(rA, c0_)], sh[0], sl[0]);
        splitu(sS [SW_A(rB, c0_)], sh[1], sl[1]);
        splitu(sS [SW_A(rA, c1_)], sh[2], sl[2]);
        splitu(sS [SW_A(rB, c1_)], sh[3], sl[3]);
        splitu(sES[SW_A(rA, c0_)], eh[0], el[0]);
        splitu(sES[SW_A(rB, c0_)], eh[1], el[1]);
        splitu(sES[SW_A(rA, c1_)], eh[2], el[2]);
        splitu(sES[SW_A(rB, c1_)], eh[3], el[3]);

#pragma unroll
        for (int nt = 0; nt < 4; nt++) {
            int ncol = nb + nt * 8 + g;
            int b0i = SW_W(k8 + c, ncol);
            int b1i = SW_W(k8 + c + 4, ncol);
            uint32_t wh0 = __float_as_uint(sWGH[b0i]);
            uint32_t wh1 = __float_as_uint(sWGH[b1i]);
            uint32_t wl0 = __float_as_uint(sWGL[b0i]);
            uint32_t wl1 = __float_as_uint(sWGL[b1i]);
            mma_tf32(cg[nt], sl[0], sl[1], sl[2], sl[3], wh0, wh1);
            mma_tf32(cg[nt], sh[0], sh[1], sh[2], sh[3], wl0, wl1);
            mma_tf32(cg[nt], sh[0], sh[1], sh[2], sh[3], wh0, wh1);

            uint32_t vh0 = __float_as_uint(sWBH[b0i]);
            uint32_t vh1 = __float_as_uint(sWBH[b1i]);
            uint32_t vl0 = __float_as_uint(sWBL[b0i]);
            uint32_t vl1 = __float_as_uint(sWBL[b1i]);
            mma_tf32(cb[nt], el[0], el[1], el[2], el[3], vh0, vh1);
            mma_tf32(cb[nt], eh[0], eh[1], eh[2], eh[3], vl0, vl1);
            mma_tf32(cb[nt], eh[0], eh[1], eh[2], eh[3], vh0, vh1);
        }
    }

    // ---- epilogue: bias + leaky + combine; l2norm; stores ----
    float2 neA[4], neB[4];
    float sA = 0.f, sB = 0.f;
#pragma unroll
    for (int nt = 0; nt < 4; nt++) {
        int col0 = nb + nt * 8 + 2 * c;
        float2 bgv = __ldg(reinterpret_cast<const float2*>(bg + col0));
        float2 bbv = __ldg(reinterpret_cast<const float2*>(bb + col0));
        float g0 = cg[nt][0] + bgv.x;  g0 = (g0 > 0.f) ? g0 : 0.2f * g0;
        float g1 = cg[nt][1] + bgv.y;  g1 = (g1 > 0.f) ? g1 : 0.2f * g1;
        float g2 = cg[nt][2] + bgv.x;  g2 = (g2 > 0.f) ? g2 : 0.2f * g2;
        float g3 = cg[nt][3] + bgv.y;  g3 = (g3 > 0.f) ? g3 : 0.2f * g3;
        float h0 = cb[nt][0] + bbv.x;  h0 = (h0 > 0.f) ? h0 : 0.2f * h0;
        float h1 = cb[nt][1] + bbv.y;  h1 = (h1 > 0.f) ? h1 : 0.2f * h1;
        float h2 = cb[nt][2] + bbv.x;  h2 = (h2 > 0.f) ? h2 : 0.2f * h2;
        float h3 = cb[nt][3] + bbv.y;  h3 = (h3 > 0.f) ? h3 : 0.2f * h3;
        float a0 = g0 + h0, a1 = g1 + h1;
        float b0 = g2 + h2, b1 = g3 + h3;
        neA[nt] = make_float2(a0, a1);
        neB[nt] = make_float2(b0, b1);
        sA = fmaf(a0, a0, fmaf(a1, a1, sA));
        sB = fmaf(b0, b0, fmaf(b1, b1, sB));
    }
    sA += __shfl_xor_sync(0xffffffffu, sA, 1);
    sA += __shfl_xor_sync(0xffffffffu, sA, 2);
    sB += __shfl_xor_sync(0xffffffffu, sB, 1);
    sB += __shfl_xor_sync(0xffffffffu, sB, 2);
    if (c == 0) {
        sSQ[wy * 64 + r0 + g]     = sA;
        sSQ[wy * 64 + r0 + g + 8] = sB;
    }
    __syncthreads();
    float totA = sSQ[r0 + g]     + sSQ[64 + r0 + g];
    float totB = sSQ[r0 + g + 8] + sSQ[64 + r0 + g + 8];
    float invA = 1.f / fmaxf(sqrtf(totA), 1e-12f);
    float invB = 1.f / fmaxf(sqrtf(totB), 1e-12f);

    int growA = rowbase + r0 + g;
    int growB = growA + 8;
#pragma unroll
    for (int nt = 0; nt < 4; nt++) {
        int col0 = nb + nt * 8 + 2 * c;
        if (growA < NN) {
            *reinterpret_cast<float2*>(&dst[growA * 64 + col0]) = neA[nt];
            *reinterpret_cast<float2*>(&out[growA * 256 + koff + col0]) =
                make_float2(neA[nt].x * invA, neA[nt].y * invA);
        }
        if (growB < NN) {
            *reinterpret_cast<float2*>(&dst[growB * 64 + col0]) = neB[nt];
            *reinterpret_cast<float2*>(&out[growB * 256 + koff + col0]) =
                make_float2(neB[nt].x * invB, neB[nt].y * invB);
        }
    }
}

// ---------------------------------------------------------------------------
extern "C" void kernel_launch(void* const* d_in, const int* in_sizes, int n_in,
                              void* d_out, int out_size) {
    const float* ue = (const float*)d_in[0];
    const float* ie = (const float*)d_in[1];
    const float* Wg[3] = {(const float*)d_in[2],  (const float*)d_in[6],  (const float*)d_in[10]};
    const float* bg[3] = {(const float*)d_in[3],  (const float*)d_in[7],  (const float*)d_in[11]};
    const float* Wb[3] = {(const float*)d_in[4],  (const float*)d_in[8],  (const float*)d_in[12]};
    const float* bb[3] = {(const float*)d_in[5],  (const float*)d_in[9],  (const float*)d_in[13]};
    const float* vals = (const float*)d_in[14];
    const int*   rows = (const int*)d_in[15];
    const int*   cols = (const int*)d_in[16];
    float* out = (float*)d_out;

    cudaFuncSetAttribute(layer_fused,
                         cudaFuncAttributeMaxDynamicSharedMemorySize, SMEM_BYTES);

    float* egoA;  cudaGetSymbolAddress((void**)&egoA, g_egoA);
    float* egoB;  cudaGetSymbolAddress((void**)&egoB, g_egoB);

    init_kernel<<<(NN * 16 + 255) / 256, 256>>>(ue, ie, out);
    hist_kernel<<<(EE + 255) / 256, 256>>>(rows);
    scan1_kernel<<<SCAN_B, 256>>>();
    scan2_kernel<<<1, 1024>>>();
    scatter_kernel<<<(EE + 255) / 256, 256>>>(vals, rows, cols);

    float* src = egoA;
    float* dstp = egoB;
    for (int k = 0; k < 3; k++) {
        layer_fused<<<(NN + 63) / 64, 256, SMEM_BYTES>>>(
            src, Wg[k], bg[k], Wb[k], bb[k], dstp, out, (k + 1) * 64);
        float* t = src; src = dstp; dstp = t;
    }
}

// round 16
// speedup vs baseline: 2.1648x; 2.1648x over previous
#include <cuda_runtime.h>
#include <cstdint>

#define NUSER 50000
#define NITEM 100000
#define NN    150000
#define DD    64
#define EE    2400000
#define SCAN_B 586          // ceil(NN/256)

// scratch: static device globals (no runtime allocation allowed)
__device__ float g_ego[NN * DD];     // 38.4 MB
__device__ float g_side[NN * DD];    // 38.4 MB (written fully by csr_spmm)
__device__ int   g_rowptr[NN];       // block-partial exclusive scan of counts
__device__ int   g_bsum[SCAN_B];     // block offsets (exclusive)
__device__ int   g_cnt[NN];
__device__ int   g_cur[NN];
__device__ int   g_scols[EE];        // CSR-sorted cols
__device__ float g_svals[EE];        // CSR-sorted vals

// ---------------------------------------------------------------------------
// init: ego = concat(user,item); out[:,0:64] = ego (raw); zero CSR counters
// ---------------------------------------------------------------------------
__global__ void init_kernel(const float* __restrict__ ue,
                            const float* __restrict__ ie,
                            float* __restrict__ out) {
    int i4 = blockIdx.x * blockDim.x + threadIdx.x;
    if (i4 >= NN * 16) return;
    int row = i4 >> 4;
    int q   = i4 & 15;
    float4 v;
    if (row < NUSER) v = reinterpret_cast<const float4*>(ue)[i4];
    else             v = reinterpret_cast<const float4*>(ie)[i4 - NUSER * 16];
    reinterpret_cast<float4*>(g_ego)[i4] = v;
    reinterpret_cast<float4*>(out)[row * 64 + q] = v;
    if (q == 0) { g_cnt[row] = 0; g_cur[row] = 0; }
}

// ---------------------------------------------------------------------------
// CSR build: histogram -> 2-level exclusive scan -> scatter
// ---------------------------------------------------------------------------
__global__ void hist_kernel(const int* __restrict__ rows) {
    int e = blockIdx.x * blockDim.x + threadIdx.x;
    if (e < EE) atomicAdd(&g_cnt[__ldg(rows + e)], 1);
}

__global__ void scan1_kernel() {        // grid SCAN_B, block 256
    __shared__ int s[256];
    int tx = threadIdx.x;
    int i  = blockIdx.x * 256 + tx;
    int v  = (i < NN) ? g_cnt[i] : 0;
    s[tx] = v;
    __syncthreads();
#pragma unroll
    for (int off = 1; off < 256; off <<= 1) {
        int t = (tx >= off) ? s[tx - off] : 0;
        __syncthreads();
        s[tx] += t;
        __syncthreads();
    }
    if (i < NN) g_rowptr[i] = s[tx] - v;          // block-local exclusive
    if (tx == 255) g_bsum[blockIdx.x] = s[255];   // block total
}

__global__ void scan2_kernel() {        // 1 block, 1024 threads
    __shared__ int s[1024];
    int tx = threadIdx.x;
    int v  = (tx < SCAN_B) ? g_bsum[tx] : 0;
    s[tx] = v;
    __syncthreads();
#pragma unroll
    for (int off = 1; off < 1024; off <<= 1) {
        int t = (tx >= off) ? s[tx - off] : 0;
        __syncthreads();
        s[tx] += t;
        __syncthreads();
    }
    if (tx < SCAN_B) g_bsum[tx] = s[tx] - v;      // exclusive block offsets
}

__global__ void scatter_kernel(const float* __restrict__ vals,
                               const int*   __restrict__ rows,
                               const int*   __restrict__ cols) {
    int e = blockIdx.x * blockDim.x + threadIdx.x;
    if (e >= EE) return;
    int r = __ldg(rows + e);
    int pos = g_rowptr[r] + g_bsum[r >> 8] + atomicAdd(&g_cur[r], 1);
    g_scols[pos] = __ldg(cols + e);
    g_svals[pos] = __ldg(vals + e);
}

__device__ __forceinline__ int rowptr_abs(int r) {
    return (r < NN) ? (__ldg(&g_rowptr[r]) + __ldg(&g_bsum[r >> 8])) : EE;
}

// ---------------------------------------------------------------------------
// CSR SpMM, warp-per-row: side[row] = sum_e val*ego[col].  Lane = float2 of D
// (256B per row, coalesced).  4 independent accumulators break the FMA chain
// so the 4-edge chunks pipeline with MLP=4.  Plain (non-atomic) final store:
// side needs no pre-zeroing and the layer needs no side-clear.
// ---------------------------------------------------------------------------
__global__ __launch_bounds__(256) void csr_spmm(const float* __restrict__ src) {
    int warp = (blockIdx.x * blockDim.x + threadIdx.x) >> 5;
    int lane = threadIdx.x & 31;
    if (warp >= NN) return;
    int row = warp;
    int beg = rowptr_abs(row);
    int end = rowptr_abs(row + 1);
    const float2* ego2 = reinterpret_cast<const float2*>(src);

    float ax0 = 0.f, ay0 = 0.f, ax1 = 0.f, ay1 = 0.f;
    float ax2 = 0.f, ay2 = 0.f, ax3 = 0.f, ay3 = 0.f;
    int e = beg;
    for (; e + 4 <= end; e += 4) {
        int   c0 = __ldg(g_scols + e),     c1 = __ldg(g_scols + e + 1);
        int   c2 = __ldg(g_scols + e + 2), c3 = __ldg(g_scols + e + 3);
        float v0 = __ldg(g_svals + e),     v1 = __ldg(g_svals + e + 1);
        float v2 = __ldg(g_svals + e + 2), v3 = __ldg(g_svals + e + 3);
        float2 x0 = __ldg(&ego2[c0 * 32 + lane]);
        float2 x1 = __ldg(&ego2[c1 * 32 + lane]);
        float2 x2 = __ldg(&ego2[c2 * 32 + lane]);
        float2 x3 = __ldg(&ego2[c3 * 32 + lane]);
        ax0 = fmaf(v0, x0.x, ax0); ay0 = fmaf(v0, x0.y, ay0);
        ax1 = fmaf(v1, x1.x, ax1); ay1 = fmaf(v1, x1.y, ay1);
        ax2 = fmaf(v2, x2.x, ax2); ay2 = fmaf(v2, x2.y, ay2);
        ax3 = fmaf(v3, x3.x, ax3); ay3 = fmaf(v3, x3.y, ay3);
    }
    for (; e < end; e++) {
        int   c0 = __ldg(g_scols + e);
        float v0 = __ldg(g_svals + e);
        float2 x0 = __ldg(&ego2[c0 * 32 + lane]);
        ax0 = fmaf(v0, x0.x, ax0); ay0 = fmaf(v0, x0.y, ay0);
    }
    float2 r2;
    r2.x = (ax0 + ax1) + (ax2 + ax3);
    r2.y = (ay0 + ay1) + (ay2 + ay3);
    reinterpret_cast<float2*>(g_side)[row * 32 + lane] = r2;
}

// ---------------------------------------------------------------------------
// tf32 helpers
// ---------------------------------------------------------------------------
__device__ __forceinline__ uint32_t f2tf32(float f) {
    uint32_t u;
    asm("cvt.rna.tf32.f32 %0, %1;" : "=r"(u) : "f"(f));
    return u;
}
__device__ __forceinline__ void split2(float f, float& hi, float& lo) {
    uint32_t h = f2tf32(f);
    hi = __uint_as_float(h);
    lo = __uint_as_float(f2tf32(f - hi));
}
__device__ __forceinline__ void splitu(float f, uint32_t& hi, uint32_t& lo) {
    hi = f2tf32(f);
    lo = f2tf32(f - __uint_as_float(hi));
}
__device__ __forceinline__ void mma_tf32(float c[4],
                                         uint32_t a0, uint32_t a1, uint32_t a2, uint32_t a3,
                                         uint32_t b0, uint32_t b1) {
    asm volatile(
        "mma.sync.aligned.m16n8k8.row.col.f32.tf32.tf32.f32 "
        "{%0,%1,%2,%3}, {%4,%5,%6,%7}, {%8,%9}, {%0,%1,%2,%3};"
        : "+f"(c[0]), "+f"(c[1]), "+f"(c[2]), "+f"(c[3])
        : "r"(a0), "r"(a1), "r"(a2), "r"(a3), "r"(b0), "r"(b1));
}

// swizzles (float-index): conflict-free mma fragment loads, float2/4-aligned
#define SW_A(r, c)  ((r) * 64 + ((c) ^ (((r) & 7) << 2)))
#define SW_W(k, n)  ((k) * 64 + ((n) ^ (((k) & 3) << 3)))

// float4 offsets in dynamic smem (128-row tile; R9 layout)
#define OFF4_WGH 0          // 64*16 = 1024 float4 each
#define OFF4_WGL 1024
#define OFF4_WBH 2048
#define OFF4_WBL 3072
#define OFF4_S   4096       // 128*16 = 2048 float4 each
#define OFF4_ES  6144
#define OFF4_SQ  8192       // 2*128 floats = 64 float4
#define SMEM_BYTES ((8256) * 16)   // 132096 B

// ---------------------------------------------------------------------------
// Dense layer (3xTF32 mma.sync m16n8k8) — R9's proven 512-thread version,
// minus the side-clear stores (csr_spmm overwrites side fully each layer).
// ---------------------------------------------------------------------------
__global__ __launch_bounds__(512) void layer_kernel(
    const float* __restrict__ Wg, const float* __restrict__ bg,
    const float* __restrict__ Wb, const float* __restrict__ bb,
    float* __restrict__ out, int koff) {
    extern __shared__ float sm[];
    float4* sm4 = reinterpret_cast<float4*>(sm);

    int tid = threadIdx.x;
    int rowbase = blockIdx.x * 128;

    // ---- stage weights, pre-split hi/lo, swizzled ----
#pragma unroll
    for (int i = 0; i < 2; i++) {
        int id = tid + i * 512;           // float4 id, 0..1023
        int k  = id >> 4, lc = id & 15;
        int sidx = k * 16 + (lc ^ ((k & 3) << 1));   // SW_W in float4 units
        float4 wg4 = reinterpret_cast<const float4*>(Wg)[id];
        float4 wb4 = reinterpret_cast<const float4*>(Wb)[id];
        float4 h, l;
        split2(wg4.x, h.x, l.x); split2(wg4.y, h.y, l.y);
        split2(wg4.z, h.z, l.z); split2(wg4.w, h.w, l.w);
        sm4[OFF4_WGH + sidx] = h;
        sm4[OFF4_WGL + sidx] = l;
        split2(wb4.x, h.x, l.x); split2(wb4.y, h.y, l.y);
        split2(wb4.z, h.z, l.z); split2(wb4.w, h.w, l.w);
        sm4[OFF4_WBH + sidx] = h;
        sm4[OFF4_WBL + sidx] = l;
    }
    // ---- stage S / ES raw, swizzled (no side clear needed) ----
#pragma unroll
    for (int i = 0; i < 4; i++) {
        int id = tid + i * 512;           // float4 id, 0..2047
        int lr = id >> 4, lc = id & 15;
        int grow = rowbase + lr;
        float4 sv = make_float4(0.f, 0.f, 0.f, 0.f);
        float4 ev = sv;
        if (grow < NN) {
            int gi4 = grow * 16 + lc;
            sv = reinterpret_cast<float4*>(g_side)[gi4];
            ev = reinterpret_cast<float4*>(g_ego)[gi4];
        }
        int aidx = lr * 16 + (lc ^ (lr & 7));        // SW_A in float4 units
        sm4[OFF4_S  + aidx] = sv;
        sm4[OFF4_ES + aidx] =
            make_float4(ev.x * sv.x, ev.y * sv.y, ev.z * sv.z, ev.w * sv.w);
    }
    __syncthreads();

    const float* sS   = sm + OFF4_S   * 4;
    const float* sES  = sm + OFF4_ES  * 4;
    const float* sWGH = sm + OFF4_WGH * 4;
    const float* sWGL = sm + OFF4_WGL * 4;
    const float* sWBH = sm + OFF4_WBH * 4;
    const float* sWBL = sm + OFF4_WBL * 4;
    float*       sSQ  = sm + OFF4_SQ  * 4;

    int warp = tid >> 5;
    int lane = tid & 31;
    int wy = warp & 1;        // col half
    int wx = warp >> 1;       // row group 0..7
    int g  = lane >> 2;       // 0..7
    int c  = lane & 3;        // 0..3
    int r0 = wx * 16;
    int nb = wy * 32;         // n-tile base

    float cg[4][4], cb[4][4];
#pragma unroll
    for (int nt = 0; nt < 4; nt++)
#pragma unroll
        for (int i = 0; i < 4; i++) { cg[nt][i] = 0.f; cb[nt][i] = 0.f; }

#pragma unroll
    for (int k = 0; k < 8; k++) {
        int k8 = k * 8;
        int rA = r0 + g, rB = r0 + g + 8;
        int c0_ = k8 + c, c1_ = k8 + c + 4;
        uint32_t sh[4], sl[4], eh[4], el[4];
        splitu(sS [SW_A(rA, c0_)], sh[0], sl[0]);
        splitu(sS [SW_A(rB, c0_)], sh[1], sl[1]);
        splitu(sS [SW_A(rA, c1_)], sh[2], sl[2]);
        splitu(sS [SW_A(rB, c1_)], sh[3], sl[3]);
        splitu(sES[SW_A(rA, c0_)], eh[0], el[0]);
        splitu(sES[SW_A(rB, c0_)], eh[1], el[1]);
        splitu(sES[SW_A(rA, c1_)], eh[2], el[2]);
        splitu(sES[SW_A(rB, c1_)], eh[3], el[3]);

#pragma unroll
        for (int nt = 0; nt < 4; nt++) {
            int ncol = nb + nt * 8 + g;
            int b0i = SW_W(k8 + c, ncol);
            int b1i = SW_W(k8 + c + 4, ncol);
            uint32_t wh0 = __float_as_uint(sWGH[b0i]);
            uint32_t wh1 = __float_as_uint(sWGH[b1i]);
            uint32_t wl0 = __float_as_uint(sWGL[b0i]);
            uint32_t wl1 = __float_as_uint(sWGL[b1i]);
            mma_tf32(cg[nt], sl[0], sl[1], sl[2], sl[3], wh0, wh1);
            mma_tf32(cg[nt], sh[0], sh[1], sh[2], sh[3], wl0, wl1);
            mma_tf32(cg[nt], sh[0], sh[1], sh[2], sh[3], wh0, wh1);

            uint32_t vh0 = __float_as_uint(sWBH[b0i]);
            uint32_t vh1 = __float_as_uint(sWBH[b1i]);
            uint32_t vl0 = __float_as_uint(sWBL[b0i]);
            uint32_t vl1 = __float_as_uint(sWBL[b1i]);
            mma_tf32(cb[nt], el[0], el[1], el[2], el[3], vh0, vh1);
            mma_tf32(cb[nt], eh[0], eh[1], eh[2], eh[3], vl0, vl1);
            mma_tf32(cb[nt], eh[0], eh[1], eh[2], eh[3], vh0, vh1);
        }
    }

    // ---- epilogue: bias + leaky + combine; l2norm; stores ----
    float2 neA[4], neB[4];
    float sA = 0.f, sB = 0.f;
#pragma unroll
    for (int nt = 0; nt < 4; nt++) {
        int col0 = nb + nt * 8 + 2 * c;
        float2 bgv = __ldg(reinterpret_cast<const float2*>(bg + col0));
        float2 bbv = __ldg(reinterpret_cast<const float2*>(bb + col0));
        float g0 = cg[nt][0] + bgv.x;  g0 = (g0 > 0.f) ? g0 : 0.2f * g0;
        float g1 = cg[nt][1] + bgv.y;  g1 = (g1 > 0.f) ? g1 : 0.2f * g1;
        float g2 = cg[nt][2] + bgv.x;  g2 = (g2 > 0.f) ? g2 : 0.2f * g2;
        float g3 = cg[nt][3] + bgv.y;  g3 = (g3 > 0.f) ? g3 : 0.2f * g3;
        float h0 = cb[nt][0] + bbv.x;  h0 = (h0 > 0.f) ? h0 : 0.2f * h0;
        float h1 = cb[nt][1] + bbv.y;  h1 = (h1 > 0.f) ? h1 : 0.2f * h1;
        float h2 = cb[nt][2] + bbv.x;  h2 = (h2 > 0.f) ? h2 : 0.2f * h2;
        float h3 = cb[nt][3] + bbv.y;  h3 = (h3 > 0.f) ? h3 : 0.2f * h3;
        float a0 = g0 + h0, a1 = g1 + h1;
        float b0 = g2 + h2, b1 = g3 + h3;
        neA[nt] = make_float2(a0, a1);
        neB[nt] = make_float2(b0, b1);
        sA = fmaf(a0, a0, fmaf(a1, a1, sA));
        sB = fmaf(b0, b0, fmaf(b1, b1, sB));
    }
    sA += __shfl_xor_sync(0xffffffffu, sA, 1);
    sA += __shfl_xor_sync(0xffffffffu, sA, 2);
    sB += __shfl_xor_sync(0xffffffffu, sB, 1);
    sB += __shfl_xor_sync(0xffffffffu, sB, 2);
    if (c == 0) {
        sSQ[wy * 128 + r0 + g]     = sA;
        sSQ[wy * 128 + r0 + g + 8] = sB;
    }
    __syncthreads();
    float totA = sSQ[r0 + g]     + sSQ[128 + r0 + g];
    float totB = sSQ[r0 + g + 8] + sSQ[128 + r0 + g + 8];
    float invA = 1.f / fmaxf(sqrtf(totA), 1e-12f);
    float invB = 1.f / fmaxf(sqrtf(totB), 1e-12f);

    int growA = rowbase + r0 + g;
    int growB = growA + 8;
#pragma unroll
    for (int nt = 0; nt < 4; nt++) {
        int col0 = nb + nt * 8 + 2 * c;
        if (growA < NN) {
            *reinterpret_cast<float2*>(&g_ego[growA * 64 + col0]) = neA[nt];
            *reinterpret_cast<float2*>(&out[growA * 256 + koff + col0]) =
                make_float2(neA[nt].x * invA, neA[nt].y * invA);
        }
        if (growB < NN) {
            *reinterpret_cast<float2*>(&g_ego[growB * 64 + col0]) = neB[nt];
            *reinterpret_cast<float2*>(&out[growB * 256 + koff + col0]) =
                make_float2(neB[nt].x * invB, neB[nt].y * invB);
        }
    }
}

// ---------------------------------------------------------------------------
extern "C" void kernel_launch(void* const* d_in, const int* in_sizes, int n_in,
                              void* d_out, int out_size) {
    const float* ue = (const float*)d_in[0];
    const float* ie = (const float*)d_in[1];
    const float* Wg[3] = {(const float*)d_in[2],  (const float*)d_in[6],  (const float*)d_in[10]};
    const float* bg[3] = {(const float*)d_in[3],  (const float*)d_in[7],  (const float*)d_in[11]};
    const float* Wb[3] = {(const float*)d_in[4],  (const float*)d_in[8],  (const float*)d_in[12]};
    const float* bb[3] = {(const float*)d_in[5],  (const float*)d_in[9],  (const float*)d_in[13]};
    const float* vals = (const float*)d_in[14];
    const int*   rows = (const int*)d_in[15];
    const int*   cols = (const int*)d_in[16];
    float* out = (float*)d_out;

    cudaFuncSetAttribute(layer_kernel,
                         cudaFuncAttributeMaxDynamicSharedMemorySize, SMEM_BYTES);

    float* ego;  cudaGetSymbolAddress((void**)&ego, g_ego);

    // launch order: init(1) hist(2) scan1(3) scan2(4) scatter(5) csr_spmm(6)...
    // ncu -s 5 -c 1 captures csr_spmm.
    init_kernel<<<(NN * 16 + 255) / 256, 256>>>(ue, ie, out);
    hist_kernel<<<(EE + 255) / 256, 256>>>(rows);
    scan1_kernel<<<SCAN_B, 256>>>();
    scan2_kernel<<<1, 1024>>>();
    scatter_kernel<<<(EE + 255) / 256, 256>>>(vals, rows, cols);

    for (int k = 0; k < 3; k++) {
        csr_spmm<<<(NN * 32 + 255) / 256, 256>>>(ego);
        layer_kernel<<<(NN + 127) / 128, 512, SMEM_BYTES>>>(
            Wg[k], bg[k], Wb[k], bb[k], out, (k + 1) * 64);
    }
}